// round 4
// baseline (speedup 1.0000x reference)
#include <cuda_runtime.h>
#include <math.h>

// EdgeAttr: out[e][c] = sigmoid( sum_k exp(-(((d_e - mu_k)/sigma)^2)) * W[k][c] + b[c] )
// d_e = || pos[src_e] - pos[dst_e] ||, mu_k = 0.4k, sigma = 0.375
//
// Inputs (metadata order): pos [N,3] f32, edge_index [2,E] int32 (JAX x64 disabled),
//                          W [16,128] f32, b [128] f32
// Output: [E,128] f32

#define E_TILE   64
#define THREADS  256
#define HID      128
#define DC       16

__global__ __launch_bounds__(THREADS, 4)
void edge_attr_kernel(const float* __restrict__ pos,
                      const int* __restrict__ edge_index,
                      const float* __restrict__ W,
                      const float* __restrict__ bias,
                      float* __restrict__ out,
                      int n_edges)
{
    __shared__ float sW[DC][HID];      // 8 KB
    __shared__ float sB[HID];          // 0.5 KB
    __shared__ float sR[E_TILE][DC];   // 4 KB

    const int t = threadIdx.x;

    // Stage weights + bias into shared memory (coalesced)
    #pragma unroll
    for (int i = t; i < DC * HID; i += THREADS) {
        sW[i / HID][i % HID] = W[i];
    }
    if (t < HID) sB[t] = bias[t];

    const int e0 = blockIdx.x * E_TILE;

    // ---- Phase 1: RBF features for this edge tile ----
    // 4 threads per edge; each computes 4 of the 16 RBF terms.
    {
        const int el = t >> 2;          // local edge 0..63
        const int q  = t & 3;           // quarter 0..3
        const int ge = e0 + el;
        if (ge < n_edges) {
            const int i0 = edge_index[ge];
            const int i1 = edge_index[n_edges + ge];
            const float* p0 = pos + 3 * (long long)i0;
            const float* p1 = pos + 3 * (long long)i1;
            const float dx = p0[0] - p1[0];
            const float dy = p0[1] - p1[1];
            const float dz = p0[2] - p1[2];
            const float d  = sqrtf(fmaf(dx, dx, fmaf(dy, dy, dz * dz)));
            const float inv_sigma = 2.6666666667f;   // 1 / 0.375
            #pragma unroll
            for (int j4 = 0; j4 < 4; j4++) {
                const int j = q * 4 + j4;
                const float u = (d - 0.4f * (float)j) * inv_sigma;
                sR[el][j] = __expf(-u * u);
            }
        }
    }
    __syncthreads();

    // ---- Phase 2: matvec + sigmoid + store ----
    // warp w handles edges {w, w+8, ..., w+56}; lane owns 4 output columns.
    const int w = t >> 5;               // warp 0..7
    const int c = (t & 31) * 4;         // column base 0..124

    const float4 bv = make_float4(sB[c], sB[c + 1], sB[c + 2], sB[c + 3]);

    #pragma unroll
    for (int k = 0; k < 8; k++) {
        const int el = w + 8 * k;
        const int ge = e0 + el;
        if (ge >= n_edges) break;

        float4 acc = bv;
        #pragma unroll
        for (int kk = 0; kk < DC; kk++) {
            const float r = sR[el][kk];                 // smem broadcast across warp
            const float4 wv = *reinterpret_cast<const float4*>(&sW[kk][c]);
            acc.x = fmaf(r, wv.x, acc.x);
            acc.y = fmaf(r, wv.y, acc.y);
            acc.z = fmaf(r, wv.z, acc.z);
            acc.w = fmaf(r, wv.w, acc.w);
        }

        // accurate fast sigmoid: 1 / (1 + exp(-x))  (EX2 + RCP, ~2 ulp)
        acc.x = __fdividef(1.0f, 1.0f + __expf(-acc.x));
        acc.y = __fdividef(1.0f, 1.0f + __expf(-acc.y));
        acc.z = __fdividef(1.0f, 1.0f + __expf(-acc.z));
        acc.w = __fdividef(1.0f, 1.0f + __expf(-acc.w));

        *reinterpret_cast<float4*>(&out[(size_t)ge * HID + c]) = acc;  // coalesced 512B/warp
    }
}

extern "C" void kernel_launch(void* const* d_in, const int* in_sizes, int n_in,
                              void* d_out, int out_size)
{
    const float* pos = (const float*)d_in[0];
    const int*   ei  = (const int*)d_in[1];
    const float* W   = (const float*)d_in[2];
    const float* b   = (const float*)d_in[3];
    float*       out = (float*)d_out;

    const int n_edges = out_size / HID;    // [E,128] output — dtype-independent edge count
    const int blocks  = (n_edges + E_TILE - 1) / E_TILE;

    edge_attr_kernel<<<blocks, THREADS>>>(pos, ei, W, b, out, n_edges);
}

// round 5
// speedup vs baseline: 2.1899x; 2.1899x over previous
#include <cuda_runtime.h>
#include <math.h>

// EdgeAttr: out[e][c] = sigmoid( sum_k exp(-(((d_e - 0.4k)/0.375)^2)) * W[k][c] + b[c] )
// Inputs: pos [N,3] f32, edge_index [2,E] int32, W [16,128] f32, b [128] f32
// Output: [E,128] f32
//
// R4: W held in registers (64 regs/thread, lane owns 4 columns), packed f32x2 FMAs,
//     persistent grid-stride blocks, double-buffered RBF tile, 2-deep gather pipeline,
//     streaming stores.

#define THREADS 256
#define E_TILE  64
#define HID     128
#define DC      16

__device__ __forceinline__ unsigned long long pack2(float lo, float hi) {
    unsigned long long r;
    asm("mov.b64 %0, {%1, %2};" : "=l"(r) : "f"(lo), "f"(hi));
    return r;
}
__device__ __forceinline__ void unpack2(unsigned long long v, float& lo, float& hi) {
    asm("mov.b64 {%0, %1}, %2;" : "=f"(lo), "=f"(hi) : "l"(v));
}
__device__ __forceinline__ unsigned long long fma2(unsigned long long a,
                                                   unsigned long long b,
                                                   unsigned long long c) {
    unsigned long long d;
    asm("fma.rn.f32x2 %0, %1, %2, %3;" : "=l"(d) : "l"(a), "l"(b), "l"(c));
    return d;
}
__device__ __forceinline__ float fast_sigmoid(float x) {
    // 1 / (1 + 2^(-x*log2e)) : 2 MUFU + 1 FMUL + 1 FADD
    float e, r;
    asm("ex2.approx.f32 %0, %1;" : "=f"(e) : "f"(-1.4426950408889634f * x));
    asm("rcp.approx.f32 %0, %1;" : "=f"(r) : "f"(1.0f + e));
    return r;
}

__global__ __launch_bounds__(THREADS, 2)
void edge_attr_kernel(const float* __restrict__ pos,
                      const int* __restrict__ edge_index,
                      const float* __restrict__ W,
                      const float* __restrict__ bias,
                      float* __restrict__ out,
                      int n_edges, int n_tiles)
{
    __shared__ float sR[2][E_TILE][DC];   // 8 KB double-buffered RBF tile

    const int t    = threadIdx.x;
    const int lane = t & 31;
    const int w    = t >> 5;
    const int c    = lane * 4;            // this lane's 4 output columns

    // ---- W slice + bias into registers (once per block) ----
    unsigned long long wreg[2 * DC];
    #pragma unroll
    for (int kk = 0; kk < DC; kk++) {
        const float4 wv = *reinterpret_cast<const float4*>(W + kk * HID + c);
        wreg[2 * kk]     = pack2(wv.x, wv.y);
        wreg[2 * kk + 1] = pack2(wv.z, wv.w);
    }
    unsigned long long b01, b23;
    {
        const float4 bv = *reinterpret_cast<const float4*>(bias + c);
        b01 = pack2(bv.x, bv.y);
        b23 = pack2(bv.z, bv.w);
    }

    // Phase-1 role: 4 threads per edge, each computes 4 RBF terms
    const int el = t >> 2;                // local edge 0..63
    const int q  = t & 3;                 // quarter 0..3
    const long long stride = gridDim.x;

    // ---- gather pipeline registers ----
    int   ia, ib;                                   // indices, current tile
    float pax, pay, paz, pbx, pby, pbz;             // positions, current tile
    int   ia2, ib2;                                 // indices, next tile

    long long tile = blockIdx.x;
    {   // prologue: idx+pos for tile, idx for tile+stride
        int ge = (int)min(tile * E_TILE + el, (long long)n_edges - 1);
        ia = edge_index[ge];
        ib = edge_index[n_edges + ge];
        pax = pos[3 * ia]; pay = pos[3 * ia + 1]; paz = pos[3 * ia + 2];
        pbx = pos[3 * ib]; pby = pos[3 * ib + 1]; pbz = pos[3 * ib + 2];
        int ge2 = (int)min((tile + stride) * E_TILE + el, (long long)n_edges - 1);
        ia2 = edge_index[ge2];
        ib2 = edge_index[n_edges + ge2];
    }

    int buf = 0;
    for (; tile < n_tiles; tile += stride) {
        // ---- phase 1: RBF for current tile (from pipelined registers) ----
        {
            const float dx = pax - pbx, dy = pay - pby, dz = paz - pbz;
            const float d  = sqrtf(fmaf(dx, dx, fmaf(dy, dy, dz * dz)));
            #pragma unroll
            for (int j4 = 0; j4 < 4; j4++) {
                const int   j = q * 4 + j4;
                const float u = (d - 0.4f * (float)j) * 2.6666666667f;
                sR[buf][el][j] = __expf(-u * u);
            }
        }
        // ---- prefetch: pos for tile+stride, idx for tile+2*stride ----
        {
            pax = pos[3 * ia2]; pay = pos[3 * ia2 + 1]; paz = pos[3 * ia2 + 2];
            pbx = pos[3 * ib2]; pby = pos[3 * ib2 + 1]; pbz = pos[3 * ib2 + 2];
            int ge2 = (int)min((tile + 2 * stride) * E_TILE + el, (long long)n_edges - 1);
            ia2 = edge_index[ge2];
            ib2 = edge_index[n_edges + ge2];
        }
        __syncthreads();

        // ---- phase 2: matvec (W in regs, f32x2) + sigmoid + streaming store ----
        const int e0 = (int)(tile * E_TILE);
        #pragma unroll
        for (int k = 0; k < 8; k++) {
            const int elx = (w << 3) + k;
            const int ge  = e0 + elx;

            unsigned long long a0 = b01, a1 = b23;
            #pragma unroll
            for (int kq = 0; kq < 4; kq++) {
                const float4 rq = *reinterpret_cast<const float4*>(&sR[buf][elx][kq * 4]);
                unsigned long long rr;
                rr = pack2(rq.x, rq.x);
                a0 = fma2(rr, wreg[8 * kq + 0], a0); a1 = fma2(rr, wreg[8 * kq + 1], a1);
                rr = pack2(rq.y, rq.y);
                a0 = fma2(rr, wreg[8 * kq + 2], a0); a1 = fma2(rr, wreg[8 * kq + 3], a1);
                rr = pack2(rq.z, rq.z);
                a0 = fma2(rr, wreg[8 * kq + 4], a0); a1 = fma2(rr, wreg[8 * kq + 5], a1);
                rr = pack2(rq.w, rq.w);
                a0 = fma2(rr, wreg[8 * kq + 6], a0); a1 = fma2(rr, wreg[8 * kq + 7], a1);
            }

            float x0, x1, x2, x3;
            unpack2(a0, x0, x1);
            unpack2(a1, x2, x3);
            const float4 o = make_float4(fast_sigmoid(x0), fast_sigmoid(x1),
                                         fast_sigmoid(x2), fast_sigmoid(x3));
            if (ge < n_edges)
                __stcs(reinterpret_cast<float4*>(out + (size_t)ge * HID + c), o);
        }
        buf ^= 1;
    }
}

extern "C" void kernel_launch(void* const* d_in, const int* in_sizes, int n_in,
                              void* d_out, int out_size)
{
    const float* pos = (const float*)d_in[0];
    const int*   ei  = (const int*)d_in[1];
    const float* W   = (const float*)d_in[2];
    const float* b   = (const float*)d_in[3];
    float*       out = (float*)d_out;

    const int n_edges = out_size / HID;
    const int n_tiles = (n_edges + E_TILE - 1) / E_TILE;
    int blocks = 148 * 8;                    // persistent-ish grid
    if (blocks > n_tiles) blocks = n_tiles;

    edge_attr_kernel<<<blocks, THREADS>>>(pos, ei, W, b, out, n_edges, n_tiles);
}